// round 15
// baseline (speedup 1.0000x reference)
#include <cuda_runtime.h>
#include <cstdint>

// Fixed shapes: z_e [16,2048,512] -> N=32768 rows, codebook [4096,512]
#define NROWS 32768
#define DIM   512
#define KC    4096

__device__ float g_wnorm[KC];
__device__ float g_xnorm[NROWS];
__device__ float g_partial[NROWS];
__device__ int   g_used[KC];
// per-(chunk,row) partial argmin results
#define NCHUNK 32
__device__ float g_pval[NCHUNK * NROWS];
__device__ int   g_pidx[NCHUNK * NROWS];
// k-major transposed operands (sanctioned static scratch)
__device__ float g_AT[DIM * NROWS];   // AT[d][m] = z[m][d]      (64 MB)
__device__ float g_BT[DIM * KC];      // BT[d][n] = cb[n][d]     ( 8 MB)

// ---------------------------------------------------------------------------
// Fused tiled transposes (A blocks then B blocks in one launch).
// B part also zeroes g_used (folded init).
#define A_TBLKS ((DIM / 32) * (NROWS / 32))   // 16384
#define B_TBLKS ((DIM / 32) * (KC / 32))      // 2048
__global__ void transpose_kernel(const float* __restrict__ zin,
                                 const float* __restrict__ cbin) {
    __shared__ float tile[32][33];
    int b = blockIdx.x;
    if (b < A_TBLKS) {
        int c0 = (b & 15) * 32, r0 = (b >> 4) * 32;
        #pragma unroll
        for (int i = threadIdx.y; i < 32; i += 8)
            tile[i][threadIdx.x] = zin[(size_t)(r0 + i) * DIM + c0 + threadIdx.x];
        __syncthreads();
        #pragma unroll
        for (int i = threadIdx.y; i < 32; i += 8)
            g_AT[(size_t)(c0 + i) * NROWS + r0 + threadIdx.x] = tile[threadIdx.x][i];
    } else {
        int bb = b - A_TBLKS;
        int lid = bb * 256 + threadIdx.y * 32 + threadIdx.x;
        if (lid < KC) g_used[lid] = 0;
        int c0 = (bb & 15) * 32, r0 = (bb >> 4) * 32;
        #pragma unroll
        for (int i = threadIdx.y; i < 32; i += 8)
            tile[i][threadIdx.x] = cbin[(size_t)(r0 + i) * DIM + c0 + threadIdx.x];
        __syncthreads();
        #pragma unroll
        for (int i = threadIdx.y; i < 32; i += 8)
            g_BT[(size_t)(c0 + i) * KC + r0 + threadIdx.x] = tile[threadIdx.x][i];
    }
}

// ---------------------------------------------------------------------------
// Fused ||w||^2 + ||x||^2 (coalesced column reads from the k-major arrays):
// same sequential ascending-d scalar chain acc = fl(acc + fl(v*v)) -> values
// bit-identical to the reference.
#define WBLK 32
__global__ void norms_kernel() {
    int b = blockIdx.x;
    if (b < WBLK) {
        int code = b * 128 + threadIdx.x;
        float acc = 0.f;
        #pragma unroll 8
        for (int d = 0; d < DIM; d++) {
            float v = g_BT[(size_t)d * KC + code];
            acc = __fadd_rn(acc, __fmul_rn(v, v));
        }
        g_wnorm[code] = acc;
    } else {
        int row = (b - WBLK) * 128 + threadIdx.x;
        float acc = 0.f;
        #pragma unroll 8
        for (int d = 0; d < DIM; d++) {
            float v = g_AT[(size_t)d * NROWS + row];
            acc = __fadd_rn(acc, __fmul_rn(v, v));
        }
        g_xnorm[row] = acc;
    }
}

// ---------------------------------------------------------------------------
// Packed f32x2: each 32-bit half is an independent IEEE fp32 FMA chain.
__device__ __forceinline__ unsigned long long dup2(float a) {
    unsigned long long r;
    asm("mov.b64 %0, {%1, %1};" : "=l"(r) : "f"(a));
    return r;
}
__device__ __forceinline__ void fma2(unsigned long long& d,
                                     unsigned long long a,
                                     unsigned long long b) {
    asm("fma.rn.f32x2 %0, %1, %2, %0;" : "+l"(d) : "l"(a), "l"(b));
}
union U64F2 { unsigned long long u; float2 f; };

__device__ __forceinline__ void cp16(uint32_t smem, const float* g) {
    asm volatile("cp.async.cg.shared.global [%0], [%1], 16;" :: "r"(smem), "l"(g));
}

// ---------------------------------------------------------------------------
// Persistent fused fp32 GEMM + argmin — occupancy-3 configuration.
// Work = 16384 tiles: 512 row-tiles (BM=64) x 32 code-chunks (BN=128 codes).
// TN=8 halves acc registers (64) -> __launch_bounds__(128,3) -> 12 warps/SM
// (3/SMSP): LDS latency at kk boundaries is covered by two sibling warps.
// 3-buffer cp.async ring, wait_group 1, one barrier per stage (r12-validated).
//  - dot per (row,code): single ascending-k FMA chain, bit-identical to all
//    passing rounds (2 chains per fma.rn.f32x2).
//  - score: d = fl( fl(xnorm - fl(2*dot)) + wnorm )
//  - argmin: (value,index) comparator; per-chunk partials merged in gather
//    over ascending disjoint ranges == jnp.argmin first-occurrence.
#define BM 64
#define BN 128
#define BK 16
#define TM 8
#define NTILES 16384
#define VQ_GRID 456
#define TSTAGES 32              // DIM/BK stages per tile
#define A_STG (BK * BM)
#define B_STG (BK * BN)
#define SMEM_BYTES (3 * (A_STG + B_STG) * 4)   // 36864

extern __shared__ float dynsmem[];

__global__ void __launch_bounds__(128, 3)
vq_argmin_kernel() {
    float* As = dynsmem;                 // [3][BK][BM]
    float* Bs = dynsmem + 3 * A_STG;     // [3][BK][BN]

    const int tid = threadIdx.x;
    const int tx  = tid & 15;    // col group
    const int ty  = tid >> 4;    // row group (0..7)

    for (int t = blockIdx.x; t < NTILES; t += gridDim.x) {
        const int rowBase = (t >> 5) * BM;
        const int cbase   = (t & 31) * BN;

        float xn[TM];
        #pragma unroll
        for (int i = 0; i < TM; i++) xn[i] = g_xnorm[rowBase + ty * TM + i];

        auto prefetch = [&](int s) {
            int b  = s % 3;
            int dk = s * BK;
            #pragma unroll
            for (int u = 0; u < 2; u++) {                 // A: 256 x 16B
                int idx = tid + u * 128;
                int k = idx >> 4, seg = (idx & 15) * 4;
                cp16((uint32_t)__cvta_generic_to_shared(&As[b * A_STG + k * BM + seg]),
                     &g_AT[(size_t)(dk + k) * NROWS + rowBase + seg]);
            }
            #pragma unroll
            for (int u = 0; u < 4; u++) {                 // B: 512 x 16B
                int idx = tid + u * 128;
                int k = idx >> 5, seg = (idx & 31) * 4;
                cp16((uint32_t)__cvta_generic_to_shared(&Bs[b * B_STG + k * BN + seg]),
                     &g_BT[(size_t)(dk + k) * KC + cbase + seg]);
            }
        };

        prefetch(0); asm volatile("cp.async.commit_group;");
        prefetch(1); asm volatile("cp.async.commit_group;");

        unsigned long long acc[TM][4];   // [i][2j+h] = cols 4*(tx+16j)+2h+{0,1}
        #pragma unroll
        for (int i = 0; i < TM; i++)
            #pragma unroll
            for (int p = 0; p < 4; p++) acc[i][p] = 0ull;

        for (int sg = 0; sg < TSTAGES; sg++) {
            asm volatile("cp.async.wait_group 1;");
            __syncthreads();
            if (sg + 2 < TSTAGES) prefetch(sg + 2);
            asm volatile("cp.async.commit_group;");

            const float* Ab = &As[(sg % 3) * A_STG];
            const float* Bb = &Bs[(sg % 3) * B_STG];
            #pragma unroll
            for (int kk = 0; kk < BK; kk++) {
                float a[TM];
                *(float4*)&a[0] = *(const float4*)&Ab[kk * BM + ty * TM];
                *(float4*)&a[4] = *(const float4*)&Ab[kk * BM + ty * TM + 4];
                unsigned long long bq[4];
                #pragma unroll
                for (int j = 0; j < 2; j++) {
                    ulonglong2 b = *(const ulonglong2*)&Bb[kk * BN + 4 * (tx + 16 * j)];
                    bq[2 * j]     = b.x;
                    bq[2 * j + 1] = b.y;
                }
                #pragma unroll
                for (int i = 0; i < TM; i++) {
                    unsigned long long ad = dup2(a[i]);
                    #pragma unroll
                    for (int p = 0; p < 4; p++)
                        fma2(acc[i][p], ad, bq[p]);
                }
            }
        }

        // argmin epilogue: per-thread scan (reference rounding order),
        // 16-lane butterfly with (value,index) comparator.
        float bestV = 3.4e38f;   // valid on threads tx<8 (row ty*8+tx)
        int   bestI = 0x7fffffff;
        #pragma unroll
        for (int i = 0; i < TM; i++) {
            float mv = 3.4e38f; int mi = 0x7fffffff;
            #pragma unroll
            for (int j = 0; j < 2; j++) {
                #pragma unroll
                for (int h = 0; h < 2; h++) {
                    U64F2 u; u.u = acc[i][2 * j + h];
                    int c0 = cbase + 4 * (tx + 16 * j) + 2 * h;
                    float av[2] = { u.f.x, u.f.y };
                    #pragma unroll
                    for (int e = 0; e < 2; e++) {
                        int   col = c0 + e;
                        float p   = __fmul_rn(2.0f, av[e]);
                        float q   = __fsub_rn(xn[i], p);
                        float sc  = __fadd_rn(q, g_wnorm[col]);
                        if (sc < mv || (sc == mv && col < mi)) { mv = sc; mi = col; }
                    }
                }
            }
            #pragma unroll
            for (int off = 8; off > 0; off >>= 1) {
                float ov = __shfl_xor_sync(0xffffffffu, mv, off);
                int   oi = __shfl_xor_sync(0xffffffffu, mi, off);
                if (ov < mv || (ov == mv && oi < mi)) { mv = ov; mi = oi; }
            }
            if (tx == i) { bestV = mv; bestI = mi; }
        }

        if (tx < TM) {
            int r = rowBase + ty * TM + tx;
            g_pval[(t & 31) * NROWS + r] = bestV;
            g_pidx[(t & 31) * NROWS + r] = bestI;
        }
        __syncthreads();   // drain: next tile's prefetch reuses smem buffers
    }
}

// ---------------------------------------------------------------------------
// Gather: warp 0 merges the 32 per-chunk partials (ascending disjoint ranges,
// (v,i) comparator == jnp.argmin first-occurrence), broadcasts k via smem;
// then all threads emit ST output / loss partial / used flag / k-as-float.
__global__ void gather_kernel(const float* __restrict__ z,
                              const float* __restrict__ cb,
                              float* __restrict__ out) {
    __shared__ float red[128];
    __shared__ int   s_k;
    int row = blockIdx.x;
    int t   = threadIdx.x;

    if (t < 32) {
        float v = g_pval[t * NROWS + row];
        int   i = g_pidx[t * NROWS + row];
        #pragma unroll
        for (int off = 16; off > 0; off >>= 1) {
            float ov = __shfl_xor_sync(0xffffffffu, v, off);
            int   oi = __shfl_xor_sync(0xffffffffu, i, off);
            if (ov < v || (ov == v && oi < i)) { v = ov; i = oi; }
        }
        if (t == 0) s_k = i;
    }
    __syncthreads();
    int k = s_k;

    float4 w = reinterpret_cast<const float4*>(cb + (size_t)k   * DIM)[t];
    float4 x = reinterpret_cast<const float4*>(z  + (size_t)row * DIM)[t];

    float4 o;
    o.x = __fadd_rn(x.x, __fsub_rn(w.x, x.x));
    o.y = __fadd_rn(x.y, __fsub_rn(w.y, x.y));
    o.z = __fadd_rn(x.z, __fsub_rn(w.z, x.z));
    o.w = __fadd_rn(x.w, __fsub_rn(w.w, x.w));
    reinterpret_cast<float4*>(out + (size_t)row * DIM)[t] = o;

    float dx = __fsub_rn(x.x, w.x), dy = __fsub_rn(x.y, w.y);
    float dz = __fsub_rn(x.z, w.z), dw = __fsub_rn(x.w, w.w);
    red[t] = dx * dx + dy * dy + dz * dz + dw * dw;
    __syncthreads();
    #pragma unroll
    for (int off = 64; off > 0; off >>= 1) {
        if (t < off) red[t] += red[t + off];
        __syncthreads();
    }
    if (t == 0) {
        g_partial[row] = red[0];
        g_used[k] = 1;
        out[(size_t)NROWS * DIM + row] = (float)k;   // k segment
    }
}

// ---------------------------------------------------------------------------
__global__ void finalize_kernel(float* __restrict__ out) {
    __shared__ double red[1024];
    int t = threadIdx.x;

    double s = 0.0;
    for (int i = t; i < NROWS; i += 1024) s += (double)g_partial[i];
    red[t] = s;
    __syncthreads();
    #pragma unroll
    for (int off = 512; off > 0; off >>= 1) {
        if (t < off) red[t] += red[t + off];
        __syncthreads();
    }
    double lossTotal = red[0];
    __syncthreads();

    double u = 0.0;
    for (int i = t; i < KC; i += 1024) u += (double)g_used[i];
    red[t] = u;
    __syncthreads();
    #pragma unroll
    for (int off = 512; off > 0; off >>= 1) {
        if (t < off) red[t] += red[t + off];
        __syncthreads();
    }

    if (t == 0) {
        size_t base = (size_t)NROWS * DIM + NROWS;
        out[base]     = (float)(0.25 * lossTotal / ((double)NROWS * (double)DIM));
        out[base + 1] = (float)(red[0] / (double)KC);
    }
}

// ---------------------------------------------------------------------------
extern "C" void kernel_launch(void* const* d_in, const int* in_sizes, int n_in,
                              void* d_out, int out_size) {
    const float* z  = (const float*)d_in[0];   // z_e [32768, 512]
    const float* cb = (const float*)d_in[1];   // codebook [4096, 512]
    if (in_sizes[0] == KC * DIM) {             // defensive: swap if order differs
        z  = (const float*)d_in[1];
        cb = (const float*)d_in[0];
    }
    float* out = (float*)d_out;                // [z_q_st | k | vq_loss | utilization]

    cudaFuncSetAttribute(vq_argmin_kernel,
                         cudaFuncAttributeMaxDynamicSharedMemorySize, SMEM_BYTES);

    {
        dim3 blk(32, 8);
        transpose_kernel<<<A_TBLKS + B_TBLKS, blk>>>(z, cb);   // launch 1
    }
    norms_kernel<<<WBLK + NROWS / 128, 128>>>();               // launch 2
    vq_argmin_kernel<<<VQ_GRID, 128, SMEM_BYTES>>>();          // launch 3
    gather_kernel<<<NROWS, 128>>>(z, cb, out);                 // launch 4
    finalize_kernel<<<1, 1024>>>(out);                         // launch 5
}

// round 16
// speedup vs baseline: 1.0385x; 1.0385x over previous
#include <cuda_runtime.h>
#include <cstdint>

// Fixed shapes: z_e [16,2048,512] -> N=32768 rows, codebook [4096,512]
#define NROWS 32768
#define DIM   512
#define KC    4096

__device__ float g_wnorm[KC];
__device__ float g_xnorm[NROWS];
__device__ float g_partial[NROWS];
__device__ int   g_used[KC];
// per-(chunk,row) partial argmin results
#define NCHUNK 16
__device__ float g_pval[NCHUNK * NROWS];
__device__ int   g_pidx[NCHUNK * NROWS];
// k-major transposed operands (sanctioned static scratch)
__device__ float g_AT[DIM * NROWS];   // AT[d][m] = z[m][d]      (64 MB)
__device__ float g_BT[DIM * KC];      // BT[d][n] = cb[n][d]     ( 8 MB)

// ---------------------------------------------------------------------------
// Fused tiled transposes, 64x64 tiles, float4 both directions.
// B part also zeroes g_used (folded init).
#define A_TBLKS ((DIM / 64) * (NROWS / 64))   // 4096
#define B_TBLKS ((DIM / 64) * (KC / 64))      // 512
__global__ void transpose_kernel(const float* __restrict__ zin,
                                 const float* __restrict__ cbin) {
    __shared__ float tile[64][65];
    const int tx = threadIdx.x;   // 0..15
    const int ty = threadIdx.y;   // 0..15
    int b = blockIdx.x;

    const float* src;
    float* dst;
    int c0, r0, ostride;
    if (b < A_TBLKS) {
        c0 = (b & 7) * 64; r0 = (b >> 3) * 64;
        src = zin; dst = g_AT; ostride = NROWS;
    } else {
        int bb = b - A_TBLKS;
        int lid = bb * 256 + ty * 16 + tx;
        if (lid < KC) g_used[lid] = 0;
        c0 = (bb & 7) * 64; r0 = (bb >> 3) * 64;
        src = cbin; dst = g_BT; ostride = KC;
    }

    #pragma unroll
    for (int i = ty; i < 64; i += 16) {
        float4 v = *reinterpret_cast<const float4*>(
            &src[(size_t)(r0 + i) * DIM + c0 + tx * 4]);
        tile[i][tx * 4 + 0] = v.x;
        tile[i][tx * 4 + 1] = v.y;
        tile[i][tx * 4 + 2] = v.z;
        tile[i][tx * 4 + 3] = v.w;
    }
    __syncthreads();
    #pragma unroll
    for (int cc = ty; cc < 64; cc += 16) {
        float4 o;
        o.x = tile[tx * 4 + 0][cc];
        o.y = tile[tx * 4 + 1][cc];
        o.z = tile[tx * 4 + 2][cc];
        o.w = tile[tx * 4 + 3][cc];
        *reinterpret_cast<float4*>(
            &dst[(size_t)(c0 + cc) * ostride + r0 + tx * 4]) = o;
    }
}

// ---------------------------------------------------------------------------
// Fused ||w||^2 + ||x||^2 (coalesced column reads from the k-major arrays):
// same sequential ascending-d scalar chain acc = fl(acc + fl(v*v)) -> values
// bit-identical to the reference.
#define WBLK 32
__global__ void norms_kernel() {
    int b = blockIdx.x;
    if (b < WBLK) {
        int code = b * 128 + threadIdx.x;
        float acc = 0.f;
        #pragma unroll 8
        for (int d = 0; d < DIM; d++) {
            float v = g_BT[(size_t)d * KC + code];
            acc = __fadd_rn(acc, __fmul_rn(v, v));
        }
        g_wnorm[code] = acc;
    } else {
        int row = (b - WBLK) * 128 + threadIdx.x;
        float acc = 0.f;
        #pragma unroll 8
        for (int d = 0; d < DIM; d++) {
            float v = g_AT[(size_t)d * NROWS + row];
            acc = __fadd_rn(acc, __fmul_rn(v, v));
        }
        g_xnorm[row] = acc;
    }
}

// ---------------------------------------------------------------------------
// Packed f32x2: each 32-bit half is an independent IEEE fp32 FMA chain.
__device__ __forceinline__ unsigned long long dup2(float a) {
    unsigned long long r;
    asm("mov.b64 %0, {%1, %1};" : "=l"(r) : "f"(a));
    return r;
}
__device__ __forceinline__ void fma2(unsigned long long& d,
                                     unsigned long long a,
                                     unsigned long long b) {
    asm("fma.rn.f32x2 %0, %1, %2, %0;" : "+l"(d) : "l"(a), "l"(b));
}
union U64F2 { unsigned long long u; float2 f; };

__device__ __forceinline__ void cp16(uint32_t smem, const float* g) {
    asm volatile("cp.async.cg.shared.global [%0], [%1], 16;" :: "r"(smem), "l"(g));
}

// ---------------------------------------------------------------------------
// Persistent fused fp32 GEMM + argmin — round-12/14 configuration verbatim
// (best measured: 2138 us, fma 81.2%). 3-buffer cp.async ring, wait_group 1,
// one barrier per stage + trailing per-tile barrier.
// Work = 8192 tiles: 512 row-tiles (BM=64) x 16 code-chunks (BN=256 codes).
//  - dot per (row,code): single ascending-k FMA chain, bit-identical to all
//    passing rounds (2 chains per fma.rn.f32x2).
//  - score: d = fl( fl(xnorm - fl(2*dot)) + wnorm )
//  - argmin: (value,index) comparator; per-chunk partials merged in gather
//    over ascending disjoint ranges == jnp.argmin first-occurrence.
#define BM 64
#define BN 256
#define BK 16
#define TM 8
#define NTILES 8192
#define VQ_GRID 304
#define TSTAGES 32              // DIM/BK stages per tile
#define A_STG (BK * BM)
#define B_STG (BK * BN)
#define SMEM_BYTES (3 * (A_STG + B_STG) * 4)   // 61440

extern __shared__ float dynsmem[];

__global__ void __launch_bounds__(128, 2)
vq_argmin_kernel() {
    float* As = dynsmem;                 // [3][BK][BM]
    float* Bs = dynsmem + 3 * A_STG;     // [3][BK][BN]

    const int tid = threadIdx.x;
    const int tx  = tid & 15;    // col group
    const int ty  = tid >> 4;    // row group (0..7)

    for (int t = blockIdx.x; t < NTILES; t += gridDim.x) {
        const int rowBase = (t >> 4) * BM;
        const int cbase   = (t & 15) * BN;

        float xn[TM];
        #pragma unroll
        for (int i = 0; i < TM; i++) xn[i] = g_xnorm[rowBase + ty * TM + i];

        auto prefetch = [&](int s) {
            int b  = s % 3;
            int dk = s * BK;
            #pragma unroll
            for (int u = 0; u < 2; u++) {                 // A: 256 x 16B
                int idx = tid + u * 128;
                int k = idx >> 4, seg = (idx & 15) * 4;
                cp16((uint32_t)__cvta_generic_to_shared(&As[b * A_STG + k * BM + seg]),
                     &g_AT[(size_t)(dk + k) * NROWS + rowBase + seg]);
            }
            #pragma unroll
            for (int u = 0; u < 8; u++) {                 // B: 1024 x 16B
                int idx = tid + u * 128;
                int k = idx >> 6, seg = (idx & 63) * 4;
                cp16((uint32_t)__cvta_generic_to_shared(&Bs[b * B_STG + k * BN + seg]),
                     &g_BT[(size_t)(dk + k) * KC + cbase + seg]);
            }
        };

        prefetch(0); asm volatile("cp.async.commit_group;");
        prefetch(1); asm volatile("cp.async.commit_group;");

        unsigned long long acc[TM][8];
        #pragma unroll
        for (int i = 0; i < TM; i++)
            #pragma unroll
            for (int p = 0; p < 8; p++) acc[i][p] = 0ull;

        for (int sg = 0; sg < TSTAGES; sg++) {
            asm volatile("cp.async.wait_group 1;");
            __syncthreads();
            if (sg + 2 < TSTAGES) prefetch(sg + 2);
            asm volatile("cp.async.commit_group;");

            const float* Ab = &As[(sg % 3) * A_STG];
            const float* Bb = &Bs[(sg % 3) * B_STG];
            #pragma unroll
            for (int kk = 0; kk < BK; kk++) {
                float a[TM];
                *(float4*)&a[0] = *(const float4*)&Ab[kk * BM + ty * TM];
                *(float4*)&a[4] = *(const float4*)&Ab[kk * BM + ty * TM + 4];
                unsigned long long bq[8];
                #pragma unroll
                for (int j = 0; j < 4; j++) {
                    ulonglong2 b = *(const ulonglong2*)&Bb[kk * BN + 4 * (tx + 16 * j)];
                    bq[2 * j]     = b.x;
                    bq[2 * j + 1] = b.y;
                }
                #pragma unroll
                for (int i = 0; i < TM; i++) {
                    unsigned long long ad = dup2(a[i]);
                    #pragma unroll
                    for (int p = 0; p < 8; p++)
                        fma2(acc[i][p], ad, bq[p]);
                }
            }
        }

        // argmin epilogue: per-thread scan (reference rounding order),
        // 16-lane butterfly with (value,index) comparator.
        float bestV = 3.4e38f;   // valid on threads tx<8 (row ty*8+tx)
        int   bestI = 0x7fffffff;
        #pragma unroll
        for (int i = 0; i < TM; i++) {
            float mv = 3.4e38f; int mi = 0x7fffffff;
            #pragma unroll
            for (int j = 0; j < 4; j++) {
                #pragma unroll
                for (int h = 0; h < 2; h++) {
                    U64F2 u; u.u = acc[i][2 * j + h];
                    int c0 = cbase + 4 * (tx + 16 * j) + 2 * h;
                    float av[2] = { u.f.x, u.f.y };
                    #pragma unroll
                    for (int e = 0; e < 2; e++) {
                        int   col = c0 + e;
                        float p   = __fmul_rn(2.0f, av[e]);
                        float q   = __fsub_rn(xn[i], p);
                        float sc  = __fadd_rn(q, g_wnorm[col]);
                        if (sc < mv || (sc == mv && col < mi)) { mv = sc; mi = col; }
                    }
                }
            }
            #pragma unroll
            for (int off = 8; off > 0; off >>= 1) {
                float ov = __shfl_xor_sync(0xffffffffu, mv, off);
                int   oi = __shfl_xor_sync(0xffffffffu, mi, off);
                if (ov < mv || (ov == mv && oi < mi)) { mv = ov; mi = oi; }
            }
            if (tx == i) { bestV = mv; bestI = mi; }
        }

        if (tx < TM) {
            int r = rowBase + ty * TM + tx;
            g_pval[(t & 15) * NROWS + r] = bestV;
            g_pidx[(t & 15) * NROWS + r] = bestI;
        }
        __syncthreads();   // drain: next tile's prefetch reuses smem buffers
    }
}

// ---------------------------------------------------------------------------
// Gather: x loaded BEFORE the merge (independent of k) so its DRAM latency
// overlaps the warp-0 16-way partial merge ((v,i) comparator over ascending
// disjoint ranges == jnp.argmin first-occurrence). Then ST output / loss /
// used flag / k-as-float.
__global__ void gather_kernel(const float* __restrict__ z,
                              const float* __restrict__ cb,
                              float* __restrict__ out) {
    __shared__ float red[128];
    __shared__ int   s_k;
    int row = blockIdx.x;
    int t   = threadIdx.x;

    float4 x = reinterpret_cast<const float4*>(z + (size_t)row * DIM)[t];

    if (t < 32) {
        float v = 3.4e38f; int i = 0x7fffffff;
        if (t < NCHUNK) {
            v = g_pval[t * NROWS + row];
            i = g_pidx[t * NROWS + row];
        }
        #pragma unroll
        for (int off = 8; off > 0; off >>= 1) {
            float ov = __shfl_xor_sync(0xffffffffu, v, off);
            int   oi = __shfl_xor_sync(0xffffffffu, i, off);
            if (ov < v || (ov == v && oi < i)) { v = ov; i = oi; }
        }
        if (t == 0) s_k = i;
    }
    __syncthreads();
    int k = s_k;

    float4 w = reinterpret_cast<const float4*>(cb + (size_t)k * DIM)[t];

    float4 o;
    o.x = __fadd_rn(x.x, __fsub_rn(w.x, x.x));
    o.y = __fadd_rn(x.y, __fsub_rn(w.y, x.y));
    o.z = __fadd_rn(x.z, __fsub_rn(w.z, x.z));
    o.w = __fadd_rn(x.w, __fsub_rn(w.w, x.w));
    reinterpret_cast<float4*>(out + (size_t)row * DIM)[t] = o;

    float dx = __fsub_rn(x.x, w.x), dy = __fsub_rn(x.y, w.y);
    float dz = __fsub_rn(x.z, w.z), dw = __fsub_rn(x.w, w.w);
    red[t] = dx * dx + dy * dy + dz * dz + dw * dw;
    __syncthreads();
    #pragma unroll
    for (int off = 64; off > 0; off >>= 1) {
        if (t < off) red[t] += red[t + off];
        __syncthreads();
    }
    if (t == 0) {
        g_partial[row] = red[0];
        g_used[k] = 1;
        out[(size_t)NROWS * DIM + row] = (float)k;   // k segment
    }
}

// ---------------------------------------------------------------------------
__global__ void finalize_kernel(float* __restrict__ out) {
    __shared__ double red[1024];
    int t = threadIdx.x;

    double s = 0.0;
    for (int i = t; i < NROWS; i += 1024) s += (double)g_partial[i];
    red[t] = s;
    __syncthreads();
    #pragma unroll
    for (int off = 512; off > 0; off >>= 1) {
        if (t < off) red[t] += red[t + off];
        __syncthreads();
    }
    double lossTotal = red[0];
    __syncthreads();

    double u = 0.0;
    for (int i = t; i < KC; i += 1024) u += (double)g_used[i];
    red[t] = u;
    __syncthreads();
    #pragma unroll
    for (int off = 512; off > 0; off >>= 1) {
        if (t < off) red[t] += red[t + off];
        __syncthreads();
    }

    if (t == 0) {
        size_t base = (size_t)NROWS * DIM + NROWS;
        out[base]     = (float)(0.25 * lossTotal / ((double)NROWS * (double)DIM));
        out[base + 1] = (float)(red[0] / (double)KC);
    }
}

// ---------------------------------------------------------------------------
extern "C" void kernel_launch(void* const* d_in, const int* in_sizes, int n_in,
                              void* d_out, int out_size) {
    const float* z  = (const float*)d_in[0];   // z_e [32768, 512]
    const float* cb = (const float*)d_in[1];   // codebook [4096, 512]
    if (in_sizes[0] == KC * DIM) {             // defensive: swap if order differs
        z  = (const float*)d_in[1];
        cb = (const float*)d_in[0];
    }
    float* out = (float*)d_out;                // [z_q_st | k | vq_loss | utilization]

    cudaFuncSetAttribute(vq_argmin_kernel,
                         cudaFuncAttributeMaxDynamicSharedMemorySize, SMEM_BYTES);

    {
        dim3 blk(16, 16);
        transpose_kernel<<<A_TBLKS + B_TBLKS, blk>>>(z, cb);   // launch 1
    }
    norms_kernel<<<WBLK + NROWS / 128, 128>>>();               // launch 2
    vq_argmin_kernel<<<VQ_GRID, 128, SMEM_BYTES>>>();          // launch 3
    gather_kernel<<<NROWS, 128>>>(z, cb, out);                 // launch 4
    finalize_kernel<<<1, 1024>>>(out);                         // launch 5
}